// round 7
// baseline (speedup 1.0000x reference)
#include <cuda_runtime.h>
#include <math.h>

namespace {

constexpr int BS    = 16;
constexpr int NGT   = 20;
constexpr int NA    = 3;
constexpr int GS    = 76;
constexpr int NC    = 80;
constexpr int NATTR = 5 + NC;           // 85
constexpr int PLANE = GS * GS;          // 5776
constexpr int TOTAL_CELLS = BS * NA * GS * GS;  // 277248

constexpr int NBLKS = BS * NGT;         // 320 blocks, one per GT
constexpr unsigned FULL = 0xffffffffu;

__device__ float        g_part[7 * NBLKS];   // per-block partials
__device__ unsigned int g_tickets;           // zero-init; reset by last block

__device__ __forceinline__ float sigmoidf(float v) {
    return 1.0f / (1.0f + expf(-v));
}

__device__ __forceinline__ float anc_w(int a) {
    return (a == 0) ? 1.25f : (a == 1) ? 2.0f : 4.125f;
}
__device__ __forceinline__ float anc_h(int a) {
    return (a == 0) ? 1.625f : (a == 1) ? 3.75f : 2.875f;
}

__global__ __launch_bounds__(32)
void yolo_fused_kernel(const float* __restrict__ x,
                       const float* __restrict__ yt,
                       float* __restrict__ out)
{
    const int lane = threadIdx.x;
    const int b    = blockIdx.x & 15;    // batch 0..15
    const int myg  = blockIdx.x >> 4;    // GT within batch 0..19

    // ---- lane l (<20) holds geometry of GT l of this batch ---------------
    float gxL = 0, gyL = 0, gwL = 0, ghL = 0;
    int   clsL = 0, giL = 0, gjL = 0;
    float gx1L = 0, gy1L = 0, gx2L = 0, gy2L = 0, areaL = 0;
    if (lane < NGT) {
        const float* gp = yt + ((size_t)b * NGT + lane) * 5;
        gxL = gp[0] * (float)GS;
        gyL = gp[1] * (float)GS;
        gwL = gp[2] * (float)GS;
        ghL = gp[3] * (float)GS;
        clsL = (int)gp[4];
        giL = min(max((int)gxL, 0), GS - 1);
        gjL = min(max((int)gyL, 0), GS - 1);
        gx1L = gxL - gwL / 2.0f;  gy1L = gyL - ghL / 2.0f;
        gx2L = gxL + gwL / 2.0f;  gy2L = gyL + ghL / 2.0f;
        areaL = (gx2L - gx1L) * (gy2L - gy1L);
    }

    // ---- probe (GT,anchor) pairs: p = g*3 + a; only p >= 3*myg needed ----
    // (those cover my GT's argmax AND every later GT's lin for dedup)
    float iou_r[2] = { -INFINITY, -INFINITY };
    #pragma unroll
    for (int r = 0; r < 2; r++) {
        const int p = r * 32 + lane;
        const int pg = min(p / 3, NGT - 1);
        const int pa = p - pg * 3;
        const bool active = (p < NGT * NA) && (p >= 3 * myg);

        // pull GT pg's geometry (shuffles executed by all lanes)
        const int   gi   = __shfl_sync(FULL, giL,  pg);
        const int   gj   = __shfl_sync(FULL, gjL,  pg);
        const float gx1  = __shfl_sync(FULL, gx1L, pg);
        const float gy1  = __shfl_sync(FULL, gy1L, pg);
        const float gx2  = __shfl_sync(FULL, gx2L, pg);
        const float gy2  = __shfl_sync(FULL, gy2L, pg);
        const float areg = __shfl_sync(FULL, areaL, pg);

        if (active) {
            const float* xp = x + (size_t)(b * NA + pa) * NATTR * PLANE
                                + (size_t)gj * GS + gi;
            const float txp = xp[0];
            const float typ = xp[PLANE];
            const float twp = xp[2 * PLANE];
            const float thp = xp[3 * PLANE];

            const float bx = sigmoidf(txp) + (float)gi;
            const float by = sigmoidf(typ) + (float)gj;
            const float bw = expf(twp) * anc_w(pa);
            const float bh = expf(thp) * anc_h(pa);

            const float px1 = bx - bw / 2.0f, py1 = by - bh / 2.0f;
            const float px2 = bx + bw / 2.0f, py2 = by + bh / 2.0f;

            const float ix1 = fmaxf(px1, gx1), iy1 = fmaxf(py1, gy1);
            const float ix2 = fminf(px2, gx2), iy2 = fminf(py2, gy2);
            const float inter = fmaxf(ix2 - ix1, 0.0f) * fmaxf(iy2 - iy1, 0.0f);
            const float area_p = (px2 - px1) * (py2 - py1);
            iou_r[r] = inter / (area_p + areg - inter + 1e-16f);
        }
    }

    // ---- per-GT argmax at lane g (valid only for g >= myg) ---------------
    int   bestA = 0;
    float bestI = -INFINITY;
    int   linL  = -1;
    {
        const int g2 = lane;   // GT index this lane resolves
        float vi[3];
        #pragma unroll
        for (int k = 0; k < 3; k++) {
            const int p   = 3 * g2 + k;
            const int src = p & 31;
            const float v0r = __shfl_sync(FULL, iou_r[0], src);
            const float v1r = __shfl_sync(FULL, iou_r[1], src);
            vi[k] = (p < 32) ? v0r : v1r;   // lanes g2>=20 garbage, unused
        }
        bestI = vi[0];
        if (vi[1] > bestI) { bestI = vi[1]; bestA = 1; }   // first max wins
        if (vi[2] > bestI) { bestI = vi[2]; bestA = 2; }
        if (lane < NGT)
            linL = ((b * NA + bestA) * GS + gjL) * GS + giL;
    }

    // ---- broadcast my GT's results to all lanes --------------------------
    const int   linM   = __shfl_sync(FULL, linL,  myg);
    const int   bestAM = __shfl_sync(FULL, bestA, myg);
    const float bestIM = __shfl_sync(FULL, bestI, myg);
    const int   clsM   = __shfl_sync(FULL, clsL,  myg);
    const float gxM    = __shfl_sync(FULL, gxL,   myg);
    const float gyM    = __shfl_sync(FULL, gyL,   myg);
    const float gwM    = __shfl_sync(FULL, gwL,   myg);
    const float ghM    = __shfl_sync(FULL, ghL,   myg);
    const int   giM    = __shfl_sync(FULL, giL,   myg);
    const int   gjM    = __shfl_sync(FULL, gjL,   myg);

    // ---- issue phase-2 loads NOW (overlap with dedup shuffles) -----------
    const float* base = x + (size_t)(linM / PLANE) * NATTR * PLANE
                          + (linM % PLANE);
    float attr = 0.0f;
    if (lane < 5)       attr = base[(size_t)lane * PLANE];
    else if (lane == 5) attr = base[(size_t)(5 + clsM) * PLANE];

    const float v0 = base[(size_t)(5 + lane) * PLANE];
    const float v1 = base[(size_t)(5 + lane + 32) * PLANE];
    const float v2 = (lane < NC - 64) ? base[(size_t)(5 + lane + 64) * PLANE]
                                      : -INFINITY;

    // ---- dedup: JAX scatter .set -> LAST duplicate wins ------------------
    bool dup = false;
    for (int u = myg + 1; u < NGT; u++)
        dup |= (__shfl_sync(FULL, linL, u) == linM);

    float lx = 0.f, ly = 0.f, lw = 0.f, lh = 0.f;
    float lcls = 0.f, lconf = 0.f, fwin = 0.f;

    if (!dup) {
        fwin = 1.0f;

        float m = fmaxf(fmaxf(v0, v1), v2);
        #pragma unroll
        for (int o = 16; o > 0; o >>= 1)
            m = fmaxf(m, __shfl_xor_sync(FULL, m, o));

        float s = expf(v0 - m) + expf(v1 - m) +
                  ((lane < NC - 64) ? expf(v2 - m) : 0.0f);
        #pragma unroll
        for (int o = 16; o > 0; o >>= 1)
            s += __shfl_xor_sync(FULL, s, o);

        const float tx = __shfl_sync(FULL, attr, 0);
        const float ty = __shfl_sync(FULL, attr, 1);
        const float tw = __shfl_sync(FULL, attr, 2);
        const float th = __shfl_sync(FULL, attr, 3);
        const float cf = __shfl_sync(FULL, attr, 4);
        const float pk = __shfl_sync(FULL, attr, 5);

        const float dx = sigmoidf(tx) - (gxM - (float)giM);
        const float dy = sigmoidf(ty) - (gyM - (float)gjM);
        const float dw = tw - logf(gwM / anc_w(bestAM));
        const float dh = th - logf(ghM / anc_h(bestAM));
        const float dc = sigmoidf(cf) * 5.0f - bestIM * 5.0f;

        lx = dx * dx; ly = dy * dy; lw = dw * dw; lh = dh * dh;
        lconf = dc * dc;
        lcls  = (m + logf(s)) - pk;   // uniform across lanes (xor reductions)
    }

    // ---- publish partials (plain stores), ticket, last-block reduce ------
    float myv = 0.0f;
    switch (lane) {
        case 0: myv = lx;    break;
        case 1: myv = ly;    break;
        case 2: myv = lw;    break;
        case 3: myv = lh;    break;
        case 4: myv = lcls;  break;
        case 5: myv = lconf; break;
        case 6: myv = fwin;  break;
        default: break;
    }
    if (lane < 7) g_part[lane * NBLKS + blockIdx.x] = myv;
    __threadfence();   // full-warp membar drains lanes 0-6's stores

    unsigned old = 0;
    if (lane == 0) old = atomicAdd(&g_tickets, 1u);
    old = __shfl_sync(FULL, old, 0);

    if (old == NBLKS - 1) {
        __threadfence();
        float acc[7] = {0, 0, 0, 0, 0, 0, 0};
        for (int blk = lane; blk < NBLKS; blk += 32) {
            #pragma unroll
            for (int i = 0; i < 7; i++)
                acc[i] += g_part[i * NBLKS + blk];
        }
        #pragma unroll
        for (int i = 0; i < 7; i++) {
            #pragma unroll
            for (int o = 16; o > 0; o >>= 1)
                acc[i] += __shfl_xor_sync(FULL, acc[i], o);
        }
        if (lane == 0) {
            const int n_obj = (int)(acc[6] + 0.5f);
            out[0] = acc[0];  out[1] = acc[1];
            out[2] = acc[2];  out[3] = acc[3];
            out[4] = (float)((double)(TOTAL_CELLS - n_obj)
                             * (double)logf(80.0f) + (double)acc[4]);
            out[5] = acc[5];
            g_tickets = 0u;          // reset for next graph replay
            __threadfence();
        }
    }
}

} // namespace

extern "C" void kernel_launch(void* const* d_in, const int* in_sizes, int n_in,
                              void* d_out, int out_size)
{
    const float* x  = (const float*)d_in[0];   // (16, 255, 76, 76) f32
    const float* yt = (const float*)d_in[1];   // (16, 20, 5) f32
    float* out = (float*)d_out;                // 6 floats

    yolo_fused_kernel<<<NBLKS, 32>>>(x, yt, out);
}

// round 8
// speedup vs baseline: 1.3176x; 1.3176x over previous
#include <cuda_runtime.h>
#include <math.h>

namespace {

constexpr int BS    = 16;
constexpr int NGT   = 20;
constexpr int NA    = 3;
constexpr int GS    = 76;
constexpr int NC    = 80;
constexpr int NATTR = 5 + NC;           // 85
constexpr int PLANE = GS * GS;          // 5776
constexpr int TOTAL_CELLS = BS * NA * GS * GS;  // 277248

constexpr int BPB   = 4;                // blocks per batch
constexpr int GPB   = NGT / BPB;        // 5 GT-warps per block
constexpr int NBLK  = BS * BPB;         // 64 blocks
constexpr int NTHR  = GPB * 32;         // 160 threads
constexpr unsigned FULL = 0xffffffffu;

__device__ float        g_acc[7];       // zero-init; reset by last block
__device__ unsigned int g_tickets;      // zero-init; reset by last block

__device__ __forceinline__ float sigmoidf(float v) {
    return 1.0f / (1.0f + expf(-v));
}
__device__ __forceinline__ float anc_w(int a) {
    return (a == 0) ? 1.25f : (a == 1) ? 2.0f : 4.125f;
}
__device__ __forceinline__ float anc_h(int a) {
    return (a == 0) ? 1.625f : (a == 1) ? 3.75f : 2.875f;
}

__global__ __launch_bounds__(NTHR)
void yolo_fused_kernel(const float* __restrict__ x,
                       const float* __restrict__ yt,
                       float* __restrict__ out)
{
    __shared__ float s_iou[NGT * NA];       // 60 probe IoUs
    __shared__ float s_gx[NGT], s_gy[NGT], s_gw[NGT], s_gh[NGT];
    __shared__ int   s_gi[NGT], s_gj[NGT], s_cls[NGT];
    __shared__ int   s_lin[NGT], s_bestA[NGT];
    __shared__ float s_bestI[NGT];
    __shared__ float s_red[7][GPB];

    const int t    = threadIdx.x;
    const int b    = blockIdx.x >> 2;       // batch 0..15
    const int sub  = blockIdx.x & (BPB - 1);// 0..3
    const int wid  = t >> 5;                // warp 0..4
    const int lane = t & 31;

    // ---- Phase A: threads 0..59 probe (GT pg, anchor pa) -----------------
    if (t < NGT * NA) {
        const int pg = t / 3;
        const int pa = t - pg * 3;

        const float* gp = yt + ((size_t)b * NGT + pg) * 5;
        const float gx = gp[0] * (float)GS;
        const float gy = gp[1] * (float)GS;
        const float gw = gp[2] * (float)GS;
        const float gh = gp[3] * (float)GS;

        const int gi = min(max((int)gx, 0), GS - 1);
        const int gj = min(max((int)gy, 0), GS - 1);

        if (pa == 0) {
            s_gx[pg] = gx;  s_gy[pg] = gy;
            s_gw[pg] = gw;  s_gh[pg] = gh;
            s_gi[pg] = gi;  s_gj[pg] = gj;
            s_cls[pg] = (int)gp[4];
        }

        const float gx1 = gx - gw / 2.0f, gy1 = gy - gh / 2.0f;
        const float gx2 = gx + gw / 2.0f, gy2 = gy + gh / 2.0f;
        const float area_g = (gx2 - gx1) * (gy2 - gy1);

        const float* xp = x + (size_t)(b * NA + pa) * NATTR * PLANE
                            + (size_t)gj * GS + gi;
        const float txp = xp[0];
        const float typ = xp[PLANE];
        const float twp = xp[2 * PLANE];
        const float thp = xp[3 * PLANE];

        const float bx = sigmoidf(txp) + (float)gi;
        const float by = sigmoidf(typ) + (float)gj;
        const float bw = expf(twp) * anc_w(pa);
        const float bh = expf(thp) * anc_h(pa);

        const float px1 = bx - bw / 2.0f, py1 = by - bh / 2.0f;
        const float px2 = bx + bw / 2.0f, py2 = by + bh / 2.0f;

        const float ix1 = fmaxf(px1, gx1), iy1 = fmaxf(py1, gy1);
        const float ix2 = fminf(px2, gx2), iy2 = fminf(py2, gy2);
        const float inter = fmaxf(ix2 - ix1, 0.0f) * fmaxf(iy2 - iy1, 0.0f);
        const float area_p = (px2 - px1) * (py2 - py1);
        s_iou[t] = inter / (area_p + area_g - inter + 1e-16f);
    }
    __syncthreads();

    // ---- argmax per GT (threads 0..19); first max wins -> strict > -------
    if (t < NGT) {
        const float i0 = s_iou[3 * t + 0];
        const float i1 = s_iou[3 * t + 1];
        const float i2 = s_iou[3 * t + 2];
        int   bestA = 0;
        float bestI = i0;
        if (i1 > bestI) { bestI = i1; bestA = 1; }
        if (i2 > bestI) { bestI = i2; bestA = 2; }
        s_bestA[t] = bestA;
        s_bestI[t] = bestI;
        s_lin[t]   = ((b * NA + bestA) * GS + s_gj[t]) * GS + s_gi[t];
    }
    __syncthreads();

    // ---- Phase B: warp w handles GT g = sub*GPB + w ----------------------
    const int g      = sub * GPB + wid;
    const int linM   = s_lin[g];
    const int bestAM = s_bestA[g];
    const float bestIM = s_bestI[g];
    const int clsM   = s_cls[g];

    // issue phase-2 loads immediately
    const float* base = x + (size_t)(linM / PLANE) * NATTR * PLANE
                          + (linM % PLANE);
    float attr = 0.0f;
    if (lane < 5)       attr = base[(size_t)lane * PLANE];
    else if (lane == 5) attr = base[(size_t)(5 + clsM) * PLANE];

    const float v0 = base[(size_t)(5 + lane) * PLANE];
    const float v1 = base[(size_t)(5 + lane + 32) * PLANE];
    const float v2 = (lane < NC - 64) ? base[(size_t)(5 + lane + 64) * PLANE]
                                      : -INFINITY;

    // dedup: JAX scatter .set -> last flat index wins (ballot over smem)
    const bool dupL = (lane > g) && (lane < NGT) && (s_lin[lane] == linM);
    const unsigned dmask = __ballot_sync(FULL, dupL);

    float lx = 0.f, ly = 0.f, lw = 0.f, lh = 0.f;
    float lcls = 0.f, lconf = 0.f, fwin = 0.f;

    if (dmask == 0u) {   // winner
        fwin = 1.0f;

        float m = fmaxf(fmaxf(v0, v1), v2);
        #pragma unroll
        for (int o = 16; o > 0; o >>= 1)
            m = fmaxf(m, __shfl_xor_sync(FULL, m, o));

        float s = expf(v0 - m) + expf(v1 - m) +
                  ((lane < NC - 64) ? expf(v2 - m) : 0.0f);
        #pragma unroll
        for (int o = 16; o > 0; o >>= 1)
            s += __shfl_xor_sync(FULL, s, o);

        const float tx = __shfl_sync(FULL, attr, 0);
        const float ty = __shfl_sync(FULL, attr, 1);
        const float tw = __shfl_sync(FULL, attr, 2);
        const float th = __shfl_sync(FULL, attr, 3);
        const float cf = __shfl_sync(FULL, attr, 4);
        const float pk = __shfl_sync(FULL, attr, 5);

        const float dx = sigmoidf(tx) - (s_gx[g] - (float)s_gi[g]);
        const float dy = sigmoidf(ty) - (s_gy[g] - (float)s_gj[g]);
        const float dw = tw - logf(s_gw[g] / anc_w(bestAM));
        const float dh = th - logf(s_gh[g] / anc_h(bestAM));
        const float dc = sigmoidf(cf) * 5.0f - bestIM * 5.0f;

        lx = dx * dx; ly = dy * dy; lw = dw * dw; lh = dh * dh;
        lconf = dc * dc;
        lcls  = (m + logf(s)) - pk;
    }

    // ---- block reduce over 5 warps + global accumulate -------------------
    if (lane == 0) {
        s_red[0][wid] = lx;   s_red[1][wid] = ly;
        s_red[2][wid] = lw;   s_red[3][wid] = lh;
        s_red[4][wid] = lcls; s_red[5][wid] = lconf;
        s_red[6][wid] = fwin;
    }
    __syncthreads();

    if (t < 7) {
        float s = 0.0f;
        #pragma unroll
        for (int w = 0; w < GPB; w++) s += s_red[t][w];
        atomicAdd(&g_acc[t], s);
    }
    __syncthreads();

    if (t == 0) {
        __threadfence();
        const unsigned old = atomicAdd(&g_tickets, 1u);
        if (old == NBLK - 1) {
            __threadfence();
            volatile float* acc = g_acc;
            const float ax = acc[0], ay = acc[1], aw = acc[2], ah = acc[3];
            const float acls = acc[4], aconf = acc[5], awin = acc[6];
            const int n_obj = (int)(awin + 0.5f);

            out[0] = ax;  out[1] = ay;  out[2] = aw;  out[3] = ah;
            out[4] = (float)((double)(TOTAL_CELLS - n_obj)
                             * (double)logf(80.0f) + (double)acls);
            out[5] = aconf;

            #pragma unroll
            for (int i = 0; i < 7; i++) g_acc[i] = 0.0f;
            g_tickets = 0u;          // reset for next graph replay
            __threadfence();
        }
    }
}

} // namespace

extern "C" void kernel_launch(void* const* d_in, const int* in_sizes, int n_in,
                              void* d_out, int out_size)
{
    const float* x  = (const float*)d_in[0];   // (16, 255, 76, 76) f32
    const float* yt = (const float*)d_in[1];   // (16, 20, 5) f32
    float* out = (float*)d_out;                // 6 floats

    yolo_fused_kernel<<<NBLK, NTHR>>>(x, yt, out);
}